// round 3
// baseline (speedup 1.0000x reference)
#include <cuda_runtime.h>
#include <cstdint>

#define N_NODE 100000
#define N_EDGE 800000
#define EMB 128

typedef unsigned long long ull;

// ---------------- static device scratch (allocation-free) ----------------
__device__ float g_h0[N_NODE * EMB];
__device__ float g_h1[N_NODE * EMB];
__device__ float g_n0[N_NODE * EMB];
__device__ float g_n1[N_NODE * EMB];
__device__ float g_E11[N_NODE * EMB];
__device__ float g_E01[N_NODE * EMB];
__device__ float g_E10[N_NODE * EMB];
__device__ float g_E00[N_NODE * EMB];
__device__ float g_a11[N_NODE * EMB];
__device__ float g_cat0[N_NODE * 256];   // [agg10 | agg00]
__device__ float g_cat1[N_NODE * 384];   // [T(256) | agg01(128)]
__device__ float g_stats[1024];

// ---------------- tiny utility kernels ----------------
__global__ void k_zero(float* __restrict__ p, int n4) {
    float4 z = make_float4(0.f, 0.f, 0.f, 0.f);
    for (int i = blockIdx.x * blockDim.x + threadIdx.x; i < n4;
         i += gridDim.x * blockDim.x)
        reinterpret_cast<float4*>(p)[i] = z;
}

// cat0 row r: cols [0,128) <- E10, cols [128,256) <- E00
__global__ void k_init_cat0(float* __restrict__ cat,
                            const float* __restrict__ E10,
                            const float* __restrict__ E00) {
    const int n = N_NODE * 32;  // float4 count per half
    for (int i = blockIdx.x * blockDim.x + threadIdx.x; i < n;
         i += gridDim.x * blockDim.x) {
        int r = i >> 5, c = i & 31;
        reinterpret_cast<float4*>(cat)[r * 64 + c] =
            reinterpret_cast<const float4*>(E10)[i];
        reinterpret_cast<float4*>(cat)[r * 64 + 32 + c] =
            reinterpret_cast<const float4*>(E00)[i];
    }
}

// cat1 row r: cols [256,384) <- E01
__global__ void k_init_cat1(float* __restrict__ cat, const float* __restrict__ E01) {
    const int n = N_NODE * 32;
    for (int i = blockIdx.x * blockDim.x + threadIdx.x; i < n;
         i += gridDim.x * blockDim.x) {
        int r = i >> 5, c = i & 31;
        reinterpret_cast<float4*>(cat)[r * 96 + 64 + c] =
            reinterpret_cast<const float4*>(E01)[i];
    }
}

// a11 = E11 + 1.1*h1   (GIN self-term fused with init)
__global__ void k_init_a11(float* __restrict__ a, const float* __restrict__ E,
                           const float* __restrict__ h, int n4) {
    for (int i = blockIdx.x * blockDim.x + threadIdx.x; i < n4;
         i += gridDim.x * blockDim.x) {
        float4 ev = reinterpret_cast<const float4*>(E)[i];
        float4 hv = reinterpret_cast<const float4*>(h)[i];
        ev.x += 1.1f * hv.x; ev.y += 1.1f * hv.y;
        ev.z += 1.1f * hv.z; ev.w += 1.1f * hv.w;
        reinterpret_cast<float4*>(a)[i] = ev;
    }
}

__device__ __forceinline__ void red_add_v4(float* p, float4 v) {
    asm volatile("red.global.add.v4.f32 [%0], {%1,%2,%3,%4};"
                 :: "l"(p), "f"(v.x), "f"(v.y), "f"(v.z), "f"(v.w)
                 : "memory");
}

// ---------------- per-edge fused (ea @ We + be) scatter-add (layer-invariant) ----------------
__global__ void k_edge_embed(const float* __restrict__ ea, const int* __restrict__ dst,
                             const float* __restrict__ We, const float* __restrict__ be,
                             float* __restrict__ Eagg) {
    __shared__ float sW[16 * EMB];
    for (int i = threadIdx.x; i < 16 * EMB; i += blockDim.x) sW[i] = We[i];
    __syncthreads();
    const int lane = threadIdx.x & 31;
    const int warp = (blockIdx.x * blockDim.x + threadIdx.x) >> 5;
    const int nwarp = (gridDim.x * blockDim.x) >> 5;
    const int c0 = lane * 4;
    const float4 bev = *reinterpret_cast<const float4*>(be + c0);
    for (int e = warp; e < N_EDGE; e += nwarp) {
        float av = (lane < 16) ? ea[(size_t)e * 16 + lane] : 0.f;
        float4 acc = bev;
#pragma unroll
        for (int k = 0; k < 16; k++) {
            float a = __shfl_sync(0xffffffffu, av, k);
            float4 w = *reinterpret_cast<const float4*>(sW + k * EMB + c0);
            acc.x += a * w.x; acc.y += a * w.y; acc.z += a * w.z; acc.w += a * w.w;
        }
        int d = dst[e];
        red_add_v4(Eagg + (size_t)d * EMB + c0, acc);
    }
}

// ---------------- per-layer node gather/scatter: agg[dst*ldc+off] += h[src] ----------------
__global__ void k_scatter(const float* __restrict__ h, const int* __restrict__ src,
                          const int* __restrict__ dst, float* __restrict__ agg,
                          int ldc, int coloff) {
    const int lane = threadIdx.x & 31;
    const int warp = (blockIdx.x * blockDim.x + threadIdx.x) >> 5;
    if (warp >= N_EDGE) return;
    int s = __ldg(&src[warp]);
    int d = __ldg(&dst[warp]);
    float4 v = *reinterpret_cast<const float4*>(h + (size_t)s * EMB + lane * 4);
    red_add_v4(agg + (size_t)d * ldc + coloff + lane * 4, v);
}

// ---------------- f32x2 packed-FMA SGEMM ----------------
// C[M,N](ldc) = maybe_relu( A[M,K](lda) @ Bcat + s1*bias1 + s2*bias2 )
// Bcat rows [0,Kb) = s1*B1, rows [Kb,K) = s2*B2 (scaling applied on smem load)
__device__ __forceinline__ void ffma2(ull& d, ull a, ull b) {
    asm("fma.rn.f32x2 %0, %1, %2, %0;" : "+l"(d) : "l"(a), "l"(b));
}

__global__ __launch_bounds__(256) void k_sgemm(
    const float* __restrict__ A, int lda,
    const float* __restrict__ B1, const float* __restrict__ B2, int Kb,
    float s1, float s2,
    const float* __restrict__ bias1, const float* __restrict__ bias2,
    float* __restrict__ C, int ldc,
    int M, int K, int N, int relu) {
    __shared__ float As[8][256];   // duplicated: As[k][2m] = As[k][2m+1] = A[m][k]
    __shared__ float Bs[8][128];
    const int t = threadIdx.x;
    const int rowBase = blockIdx.y * 128;
    const int colBase = blockIdx.x * 128;
    const int arow = t >> 1, acol = (t & 1) * 4;
    const int brow = t >> 5, bcol = (t & 31) * 4;
    const int ty = t >> 4, tx = t & 15;

    ull acc2[8][4];
#pragma unroll
    for (int i = 0; i < 8; i++)
#pragma unroll
        for (int j = 0; j < 4; j++) acc2[i][j] = 0ull;

    for (int k0 = 0; k0 < K; k0 += 8) {
        // A tile (duplicated store)
        float4 av = make_float4(0.f, 0.f, 0.f, 0.f);
        int gr = rowBase + arow;
        if (gr < M)
            av = *reinterpret_cast<const float4*>(A + (size_t)gr * lda + k0 + acol);
        *reinterpret_cast<float2*>(&As[acol + 0][2 * arow]) = make_float2(av.x, av.x);
        *reinterpret_cast<float2*>(&As[acol + 1][2 * arow]) = make_float2(av.y, av.y);
        *reinterpret_cast<float2*>(&As[acol + 2][2 * arow]) = make_float2(av.z, av.z);
        *reinterpret_cast<float2*>(&As[acol + 3][2 * arow]) = make_float2(av.w, av.w);
        // B tile (two stacked sources, row-scaled)
        {
            int row = k0 + brow;
            const float* Bsrc;
            float sc;
            if (row < Kb) { Bsrc = B1 + (size_t)row * N; sc = s1; }
            else          { Bsrc = B2 + (size_t)(row - Kb) * N; sc = s2; }
            float4 bv = *reinterpret_cast<const float4*>(Bsrc + colBase + bcol);
            bv.x *= sc; bv.y *= sc; bv.z *= sc; bv.w *= sc;
            *reinterpret_cast<float4*>(&Bs[brow][bcol]) = bv;
        }
        __syncthreads();
#pragma unroll
        for (int k = 0; k < 8; k++) {
            ull a2[8], b2[4];
            const ull* ap = reinterpret_cast<const ull*>(&As[k][ty * 16]);
            const ull* bp = reinterpret_cast<const ull*>(&Bs[k][tx * 8]);
#pragma unroll
            for (int i = 0; i < 8; i++) a2[i] = ap[i];
#pragma unroll
            for (int j = 0; j < 4; j++) b2[j] = bp[j];
#pragma unroll
            for (int i = 0; i < 8; i++)
#pragma unroll
                for (int j = 0; j < 4; j++) ffma2(acc2[i][j], a2[i], b2[j]);
        }
        __syncthreads();
    }

#pragma unroll
    for (int i = 0; i < 8; i++) {
        int gr = rowBase + ty * 8 + i;
        if (gr < M) {
#pragma unroll
            for (int j = 0; j < 2; j++) {
                int gc = colBase + tx * 8 + j * 4;
                float4 bb1 = *reinterpret_cast<const float4*>(bias1 + gc);
                float4 bb2 = *reinterpret_cast<const float4*>(bias2 + gc);
                float c0, c1, c2, c3;
                asm("mov.b64 {%0,%1}, %2;" : "=f"(c0), "=f"(c1) : "l"(acc2[i][2 * j]));
                asm("mov.b64 {%0,%1}, %2;" : "=f"(c2), "=f"(c3) : "l"(acc2[i][2 * j + 1]));
                float4 v;
                v.x = c0 + s1 * bb1.x + s2 * bb2.x;
                v.y = c1 + s1 * bb1.y + s2 * bb2.y;
                v.z = c2 + s1 * bb1.z + s2 * bb2.z;
                v.w = c3 + s1 * bb1.w + s2 * bb2.w;
                if (relu) {
                    v.x = fmaxf(v.x, 0.f); v.y = fmaxf(v.y, 0.f);
                    v.z = fmaxf(v.z, 0.f); v.w = fmaxf(v.w, 0.f);
                }
                *reinterpret_cast<float4*>(C + (size_t)gr * ldc + gc) = v;
            }
        }
    }
}

// ---------------- BatchNorm (training-mode batch stats, biased variance) ----------------
__global__ void k_bn_stats(const float* __restrict__ X, int M, float* __restrict__ stats) {
    const int col = threadIdx.x & 127;
    const int rp = threadIdx.x >> 7;
    float s = 0.f, q = 0.f;
    for (int r = blockIdx.x * 2 + rp; r < M; r += gridDim.x * 2) {
        float v = X[(size_t)r * EMB + col];
        s += v; q += v * v;
    }
    atomicAdd(&stats[col], s);
    atomicAdd(&stats[EMB + col], q);
}

__global__ void k_bn_finalize(float* __restrict__ stats, const float* __restrict__ gamma,
                              const float* __restrict__ beta, int layer, float invM) {
    int c = threadIdx.x;
    int type = c >> 7, col = c & 127;
    float mu = stats[type * 256 + col] * invM;
    float var = stats[type * 256 + 128 + col] * invM - mu * mu;
    float a = gamma[layer * EMB + col] * rsqrtf(var + 1e-5f);
    float b = beta[layer * EMB + col] - a * mu;
    stats[512 + type * 256 + col] = a;
    stats[512 + type * 256 + 128 + col] = b;
}

__global__ void k_bn_apply(const float* __restrict__ X, float* __restrict__ Y, int M,
                           const float* __restrict__ coef, int relu) {
    const int n = M * EMB;
    for (int i = blockIdx.x * blockDim.x + threadIdx.x; i < n;
         i += gridDim.x * blockDim.x) {
        int col = i & 127;
        float v = coef[col] * X[i] + coef[128 + col];
        if (relu) v = fmaxf(v, 0.f);
        Y[i] = v;
    }
}

// ---------------- host orchestration ----------------
extern "C" void kernel_launch(void* const* d_in, const int* in_sizes, int n_in,
                              void* d_out, int out_size) {
    (void)in_sizes; (void)n_in; (void)out_size;
    const float* x0   = (const float*)d_in[0];
    const float* x1   = (const float*)d_in[1];
    const float* ea11 = (const float*)d_in[2];
    const float* ea10 = (const float*)d_in[3];
    const float* ea01 = (const float*)d_in[4];
    const float* ea00 = (const float*)d_in[5];
    const int*   ei11 = (const int*)d_in[6];
    const int*   ei10 = (const int*)d_in[7];
    const int*   ei01 = (const int*)d_in[8];
    const int*   ei00 = (const int*)d_in[9];
    const float* Wx  = (const float*)d_in[10];
    const float* bx  = (const float*)d_in[11];
    const float* We  = (const float*)d_in[12];
    const float* be  = (const float*)d_in[13];
    const float* gW1 = (const float*)d_in[14];
    const float* gb1 = (const float*)d_in[15];
    const float* gW2 = (const float*)d_in[16];
    const float* gb2 = (const float*)d_in[17];
    const float* W10 = (const float*)d_in[18];
    const float* b10 = (const float*)d_in[19];
    const float* W01 = (const float*)d_in[20];
    const float* b01 = (const float*)d_in[21];
    const float* W00 = (const float*)d_in[22];
    const float* b00 = (const float*)d_in[23];
    const float* gamma = (const float*)d_in[24];
    const float* beta  = (const float*)d_in[25];
    float* out = (float*)d_out;

    float *h0, *h1, *n0b, *n1b, *E11, *E01, *E10, *E00, *a11, *cat0, *cat1, *stats;
    cudaGetSymbolAddress((void**)&h0,   g_h0);
    cudaGetSymbolAddress((void**)&h1,   g_h1);
    cudaGetSymbolAddress((void**)&n0b,  g_n0);
    cudaGetSymbolAddress((void**)&n1b,  g_n1);
    cudaGetSymbolAddress((void**)&E11,  g_E11);
    cudaGetSymbolAddress((void**)&E01,  g_E01);
    cudaGetSymbolAddress((void**)&E10,  g_E10);
    cudaGetSymbolAddress((void**)&E00,  g_E00);
    cudaGetSymbolAddress((void**)&a11,  g_a11);
    cudaGetSymbolAddress((void**)&cat0, g_cat0);
    cudaGetSymbolAddress((void**)&cat1, g_cat1);
    cudaGetSymbolAddress((void**)&stats, g_stats);

    const int n4 = N_NODE * EMB / 4;

    // Layer-invariant edge-embedding aggregates: E[d] = sum_{e->d} (ea[e]@We + be)
    k_zero<<<2048, 256>>>(E11, n4);
    k_zero<<<2048, 256>>>(E01, n4);
    k_zero<<<2048, 256>>>(E10, n4);
    k_zero<<<2048, 256>>>(E00, n4);
    k_edge_embed<<<2048, 256>>>(ea11, ei11 + N_EDGE, We, be, E11);
    k_edge_embed<<<2048, 256>>>(ea01, ei01 + N_EDGE, We, be, E01);
    k_edge_embed<<<2048, 256>>>(ea10, ei10 + N_EDGE, We, be, E10);
    k_edge_embed<<<2048, 256>>>(ea00, ei00 + N_EDGE, We, be, E00);

    // Input embeddings: h = x @ Wx + bx
    dim3 g1(1, (N_NODE + 127) / 128);
    dim3 g2(2, (N_NODE + 127) / 128);
    k_sgemm<<<g1, 256>>>(x0, 256, Wx, Wx, 256, 1.f, 0.f, bx, bx, h0, 128,
                         N_NODE, 256, 128, 0);
    k_sgemm<<<g1, 256>>>(x1, 256, Wx, Wx, 256, 1.f, 0.f, bx, bx, h1, 128,
                         N_NODE, 256, 128, 0);

    const int sgrid = (N_EDGE * 32) / 256;  // 1 warp per edge
    float* cur0 = h0;
    float* cur1 = h1;

    for (int layer = 0; layer < 2; layer++) {
        float* o0 = (layer == 0) ? n0b : h0;
        float* o1 = (layer == 0) ? n1b : h1;

        // init aggregation buffers from layer-invariant E (+ GIN self term)
        k_init_cat0<<<2048, 256>>>(cat0, E10, E00);
        k_init_cat1<<<2048, 256>>>(cat1, E01);
        k_init_a11<<<2048, 256>>>(a11, E11, cur1, n4);

        // scatter node features: agg[dst] += h[src]
        k_scatter<<<sgrid, 256>>>(cur1, ei11, ei11 + N_EDGE, a11, 128, 0);
        k_scatter<<<sgrid, 256>>>(cur0, ei01, ei01 + N_EDGE, cat1, 384, 256);
        k_scatter<<<sgrid, 256>>>(cur1, ei10, ei10 + N_EDGE, cat0, 256, 0);
        k_scatter<<<sgrid, 256>>>(cur0, ei00, ei00 + N_EDGE, cat0, 256, 128);

        // T = relu(a11 @ gW1 + gb1)  -> cat1 cols [0,256)
        k_sgemm<<<g2, 256>>>(a11, 128, gW1, gW1, 128, 1.f, 0.f, gb1, gb1,
                             cat1, 384, N_NODE, 128, 256, 1);
        // new1 = [T | a01] @ [0.5*gW2 ; 0.05*W01] + 0.5*gb2 + 0.05*b01
        k_sgemm<<<g1, 256>>>(cat1, 384, gW2, W01, 256, 0.5f, 0.05f, gb2, b01,
                             o1, 128, N_NODE, 384, 128, 0);
        // new0 = [a10 | a00] @ [0.05*W10 ; 0.05*W00] + 0.05*(b10+b00)
        k_sgemm<<<g1, 256>>>(cat0, 256, W10, W00, 128, 0.05f, 0.05f, b10, b00,
                             o0, 128, N_NODE, 256, 128, 0);

        // BatchNorm per node type; last layer writes straight to d_out
        k_zero<<<1, 128>>>(stats, 128);
        k_bn_stats<<<1024, 256>>>(o0, N_NODE, stats);
        k_bn_stats<<<1024, 256>>>(o1, N_NODE, stats + 256);
        k_bn_finalize<<<1, 256>>>(stats, gamma, beta, layer, 1.f / N_NODE);
        int relu = (layer == 0) ? 1 : 0;
        float* dst0 = (layer == 0) ? o0 : out;
        float* dst1 = (layer == 0) ? o1 : out + (size_t)N_NODE * EMB;
        k_bn_apply<<<2048, 256>>>(o0, dst0, N_NODE, stats + 512, relu);
        k_bn_apply<<<2048, 256>>>(o1, dst1, N_NODE, stats + 768, relu);

        cur0 = o0;
        cur1 = o1;
    }
}

// round 4
// speedup vs baseline: 1.1304x; 1.1304x over previous
#include <cuda_runtime.h>
#include <cstdint>

#define N_NODE 100000
#define N_EDGE 800000
#define EMB 128

typedef unsigned long long ull;

// ---------------- static device scratch (allocation-free) ----------------
__device__ float g_h0[N_NODE * EMB];
__device__ float g_h1[N_NODE * EMB];
__device__ float g_n0[N_NODE * EMB];
__device__ float g_n1[N_NODE * EMB];
__device__ float g_E11[N_NODE * EMB];
__device__ float g_E01[N_NODE * EMB];
__device__ float g_E10[N_NODE * EMB];
__device__ float g_E00[N_NODE * EMB];
__device__ float g_a11[N_NODE * EMB];
__device__ float g_cat0[N_NODE * 256];   // [agg10 | agg00]
__device__ float g_cat1[N_NODE * 384];   // [T(256) | agg01(128)]
__device__ float g_stats[1024];

// ---------------- tiny utility kernels ----------------
__global__ void k_zero(float* __restrict__ p, int n4) {
    float4 z = make_float4(0.f, 0.f, 0.f, 0.f);
    for (int i = blockIdx.x * blockDim.x + threadIdx.x; i < n4;
         i += gridDim.x * blockDim.x)
        reinterpret_cast<float4*>(p)[i] = z;
}

// cat0 row r: cols [0,128) <- E10, cols [128,256) <- E00
__global__ void k_init_cat0(float* __restrict__ cat,
                            const float* __restrict__ E10,
                            const float* __restrict__ E00) {
    const int n = N_NODE * 32;
    for (int i = blockIdx.x * blockDim.x + threadIdx.x; i < n;
         i += gridDim.x * blockDim.x) {
        int r = i >> 5, c = i & 31;
        reinterpret_cast<float4*>(cat)[r * 64 + c] =
            reinterpret_cast<const float4*>(E10)[i];
        reinterpret_cast<float4*>(cat)[r * 64 + 32 + c] =
            reinterpret_cast<const float4*>(E00)[i];
    }
}

// cat1 row r: cols [256,384) <- E01
__global__ void k_init_cat1(float* __restrict__ cat, const float* __restrict__ E01) {
    const int n = N_NODE * 32;
    for (int i = blockIdx.x * blockDim.x + threadIdx.x; i < n;
         i += gridDim.x * blockDim.x) {
        int r = i >> 5, c = i & 31;
        reinterpret_cast<float4*>(cat)[r * 96 + 64 + c] =
            reinterpret_cast<const float4*>(E01)[i];
    }
}

// a11 = E11 + 1.1*h1   (GIN self-term fused with init)
__global__ void k_init_a11(float* __restrict__ a, const float* __restrict__ E,
                           const float* __restrict__ h, int n4) {
    for (int i = blockIdx.x * blockDim.x + threadIdx.x; i < n4;
         i += gridDim.x * blockDim.x) {
        float4 ev = reinterpret_cast<const float4*>(E)[i];
        float4 hv = reinterpret_cast<const float4*>(h)[i];
        ev.x += 1.1f * hv.x; ev.y += 1.1f * hv.y;
        ev.z += 1.1f * hv.z; ev.w += 1.1f * hv.w;
        reinterpret_cast<float4*>(a)[i] = ev;
    }
}

__device__ __forceinline__ void red_add_v4(float* p, float4 v) {
    asm volatile("red.global.add.v4.f32 [%0], {%1,%2,%3,%4};"
                 :: "l"(p), "f"(v.x), "f"(v.y), "f"(v.z), "f"(v.w)
                 : "memory");
}

// ---------------- per-edge fused (ea @ We + be) scatter-add (layer-invariant) ----------------
__global__ void k_edge_embed(const float* __restrict__ ea, const int* __restrict__ dst,
                             const float* __restrict__ We, const float* __restrict__ be,
                             float* __restrict__ Eagg) {
    __shared__ float sW[16 * EMB];
    for (int i = threadIdx.x; i < 16 * EMB; i += blockDim.x) sW[i] = We[i];
    __syncthreads();
    const int lane = threadIdx.x & 31;
    const int warp = (blockIdx.x * blockDim.x + threadIdx.x) >> 5;
    const int nwarp = (gridDim.x * blockDim.x) >> 5;
    const int c0 = lane * 4;
    const float4 bev = *reinterpret_cast<const float4*>(be + c0);
    for (int e = warp; e < N_EDGE; e += nwarp) {
        float av = (lane < 16) ? ea[(size_t)e * 16 + lane] : 0.f;
        float4 acc = bev;
#pragma unroll
        for (int k = 0; k < 16; k++) {
            float a = __shfl_sync(0xffffffffu, av, k);
            float4 w = *reinterpret_cast<const float4*>(sW + k * EMB + c0);
            acc.x += a * w.x; acc.y += a * w.y; acc.z += a * w.z; acc.w += a * w.w;
        }
        int d = dst[e];
        red_add_v4(Eagg + (size_t)d * EMB + c0, acc);
    }
}

// ---------------- per-layer node gather/scatter: agg[dst*ldc+off] += h[src] ----------------
__global__ void k_scatter(const float* __restrict__ h, const int* __restrict__ src,
                          const int* __restrict__ dst, float* __restrict__ agg,
                          int ldc, int coloff) {
    const int lane = threadIdx.x & 31;
    const int warp = (blockIdx.x * blockDim.x + threadIdx.x) >> 5;
    if (warp >= N_EDGE) return;
    int s = __ldg(&src[warp]);
    int d = __ldg(&dst[warp]);
    float4 v = *reinterpret_cast<const float4*>(h + (size_t)s * EMB + lane * 4);
    red_add_v4(agg + (size_t)d * ldc + coloff + lane * 4, v);
}

// ---------------- f32x2 packed-FMA SGEMM (row-paired accumulators) ----------------
// C[M,N](ldc) = maybe_relu( A[M,K](lda) @ Bcat + s1*bias1 + s2*bias2 )
// Bcat rows [0,Kb) = s1*B1, rows [Kb,K) = s2*B2 (scaling applied on smem load)
// If statp != null (requires N==128 grid.x==1): atomically accumulate per-column
// sum into statp[col] and sum-of-squares into statp[128+col] of the OUTPUT.
__device__ __forceinline__ void ffma2(ull& d, ull a, ull b) {
    asm("fma.rn.f32x2 %0, %1, %2, %0;" : "+l"(d) : "l"(a), "l"(b));
}
__device__ __forceinline__ ull dup2(float x) {
    ull r; asm("mov.b64 %0, {%1, %1};" : "=l"(r) : "f"(x)); return r;
}

__global__ __launch_bounds__(256, 2) void k_sgemm(
    const float* __restrict__ A, int lda,
    const float* __restrict__ B1, const float* __restrict__ B2, int Kb,
    float s1, float s2,
    const float* __restrict__ bias1, const float* __restrict__ bias2,
    float* __restrict__ C, int ldc,
    int M, int K, int N, int relu, float* __restrict__ statp) {
    __shared__ float As[16][128];   // As[k][m] = A[rowBase+m][k0+k]
    __shared__ float Bs[16][128];
    __shared__ float sred[256];     // col sums / sumsq
    const int t = threadIdx.x;
    const int rowBase = blockIdx.y * 128;
    const int colBase = blockIdx.x * 128;
    const int lrow = t >> 1, lkc = (t & 1) * 8;      // A-load mapping
    const int bkk = t >> 4, bnc = (t & 15) * 8;      // B-load mapping
    const int ty = t >> 4, tx = t & 15;

    ull acc2[4][8];
#pragma unroll
    for (int i = 0; i < 4; i++)
#pragma unroll
        for (int j = 0; j < 8; j++) acc2[i][j] = 0ull;

    for (int k0 = 0; k0 < K; k0 += 16) {
        // A tile: transpose store (8 scalars per thread)
        {
            float4 av0 = make_float4(0.f, 0.f, 0.f, 0.f), av1 = av0;
            int gr = rowBase + lrow;
            if (gr < M) {
                const float* ap = A + (size_t)gr * lda + k0 + lkc;
                av0 = *reinterpret_cast<const float4*>(ap);
                av1 = *reinterpret_cast<const float4*>(ap + 4);
            }
            As[lkc + 0][lrow] = av0.x; As[lkc + 1][lrow] = av0.y;
            As[lkc + 2][lrow] = av0.z; As[lkc + 3][lrow] = av0.w;
            As[lkc + 4][lrow] = av1.x; As[lkc + 5][lrow] = av1.y;
            As[lkc + 6][lrow] = av1.z; As[lkc + 7][lrow] = av1.w;
        }
        // B tile: direct copy with row-scale
        {
            int row = k0 + bkk;
            const float* Bsrc; float sc;
            if (row < Kb) { Bsrc = B1 + (size_t)row * N; sc = s1; }
            else          { Bsrc = B2 + (size_t)(row - Kb) * N; sc = s2; }
            float4 bv0 = *reinterpret_cast<const float4*>(Bsrc + colBase + bnc);
            float4 bv1 = *reinterpret_cast<const float4*>(Bsrc + colBase + bnc + 4);
            bv0.x *= sc; bv0.y *= sc; bv0.z *= sc; bv0.w *= sc;
            bv1.x *= sc; bv1.y *= sc; bv1.z *= sc; bv1.w *= sc;
            *reinterpret_cast<float4*>(&Bs[bkk][bnc])     = bv0;
            *reinterpret_cast<float4*>(&Bs[bkk][bnc + 4]) = bv1;
        }
        __syncthreads();
#pragma unroll
        for (int kk = 0; kk < 16; kk++) {
            ull a2[4];
            const ull* ap = reinterpret_cast<const ull*>(&As[kk][ty * 8]);
#pragma unroll
            for (int i = 0; i < 4; i++) a2[i] = ap[i];
            float4 r0 = *reinterpret_cast<const float4*>(&Bs[kk][tx * 8]);
            float4 r1 = *reinterpret_cast<const float4*>(&Bs[kk][tx * 8 + 4]);
            ull b2[8];
            b2[0] = dup2(r0.x); b2[1] = dup2(r0.y);
            b2[2] = dup2(r0.z); b2[3] = dup2(r0.w);
            b2[4] = dup2(r1.x); b2[5] = dup2(r1.y);
            b2[6] = dup2(r1.z); b2[7] = dup2(r1.w);
#pragma unroll
            for (int i = 0; i < 4; i++)
#pragma unroll
                for (int j = 0; j < 8; j++) ffma2(acc2[i][j], a2[i], b2[j]);
        }
        __syncthreads();
    }

    // combined bias
    float bb[8];
#pragma unroll
    for (int j = 0; j < 8; j++) {
        int gc = colBase + tx * 8 + j;
        bb[j] = s1 * bias1[gc] + s2 * bias2[gc];
    }

    float csum[8], csq[8];
#pragma unroll
    for (int j = 0; j < 8; j++) { csum[j] = 0.f; csq[j] = 0.f; }

#pragma unroll
    for (int ip = 0; ip < 4; ip++) {
        float lo[8], hi[8];
#pragma unroll
        for (int j = 0; j < 8; j++)
            asm("mov.b64 {%0,%1}, %2;" : "=f"(lo[j]), "=f"(hi[j]) : "l"(acc2[ip][j]));
#pragma unroll
        for (int half = 0; half < 2; half++) {
            float* vv = half ? hi : lo;
            int gr = rowBase + ty * 8 + 2 * ip + half;
            if (gr < M) {
                float v[8];
#pragma unroll
                for (int j = 0; j < 8; j++) {
                    v[j] = vv[j] + bb[j];
                    if (relu) v[j] = fmaxf(v[j], 0.f);
                    csum[j] += v[j];
                    csq[j] += v[j] * v[j];
                }
                float* cp = C + (size_t)gr * ldc + colBase + tx * 8;
                *reinterpret_cast<float4*>(cp)     = make_float4(v[0], v[1], v[2], v[3]);
                *reinterpret_cast<float4*>(cp + 4) = make_float4(v[4], v[5], v[6], v[7]);
            }
        }
    }

    if (statp) {
        // smem per-column reduction, then one global atomic per column per block
        if (t < 256) { sred[t] = 0.f; }
        __syncthreads();
        int colb = tx * 8;
#pragma unroll
        for (int j = 0; j < 8; j++) {
            atomicAdd(&sred[colb + j], csum[j]);
            atomicAdd(&sred[128 + colb + j], csq[j]);
        }
        __syncthreads();
        if (t < 128) {
            atomicAdd(&statp[t], sred[t]);
            atomicAdd(&statp[128 + t], sred[128 + t]);
        }
    }
}

// ---------------- BatchNorm finalize / apply ----------------
__global__ void k_bn_finalize(float* __restrict__ stats, const float* __restrict__ gamma,
                              const float* __restrict__ beta, int layer, float invM) {
    int c = threadIdx.x;
    int type = c >> 7, col = c & 127;
    float mu = stats[type * 256 + col] * invM;
    float var = stats[type * 256 + 128 + col] * invM - mu * mu;
    float a = gamma[layer * EMB + col] * rsqrtf(var + 1e-5f);
    float b = beta[layer * EMB + col] - a * mu;
    stats[512 + type * 256 + col] = a;
    stats[512 + type * 256 + 128 + col] = b;
}

__global__ void k_bn_apply(const float* __restrict__ X, float* __restrict__ Y, int M,
                           const float* __restrict__ coef, int relu) {
    const int n = M * EMB;
    for (int i = blockIdx.x * blockDim.x + threadIdx.x; i < n;
         i += gridDim.x * blockDim.x) {
        int col = i & 127;
        float v = coef[col] * X[i] + coef[128 + col];
        if (relu) v = fmaxf(v, 0.f);
        Y[i] = v;
    }
}

// ---------------- host orchestration ----------------
extern "C" void kernel_launch(void* const* d_in, const int* in_sizes, int n_in,
                              void* d_out, int out_size) {
    (void)in_sizes; (void)n_in; (void)out_size;
    const float* x0   = (const float*)d_in[0];
    const float* x1   = (const float*)d_in[1];
    const float* ea11 = (const float*)d_in[2];
    const float* ea10 = (const float*)d_in[3];
    const float* ea01 = (const float*)d_in[4];
    const float* ea00 = (const float*)d_in[5];
    const int*   ei11 = (const int*)d_in[6];
    const int*   ei10 = (const int*)d_in[7];
    const int*   ei01 = (const int*)d_in[8];
    const int*   ei00 = (const int*)d_in[9];
    const float* Wx  = (const float*)d_in[10];
    const float* bx  = (const float*)d_in[11];
    const float* We  = (const float*)d_in[12];
    const float* be  = (const float*)d_in[13];
    const float* gW1 = (const float*)d_in[14];
    const float* gb1 = (const float*)d_in[15];
    const float* gW2 = (const float*)d_in[16];
    const float* gb2 = (const float*)d_in[17];
    const float* W10 = (const float*)d_in[18];
    const float* b10 = (const float*)d_in[19];
    const float* W01 = (const float*)d_in[20];
    const float* b01 = (const float*)d_in[21];
    const float* W00 = (const float*)d_in[22];
    const float* b00 = (const float*)d_in[23];
    const float* gamma = (const float*)d_in[24];
    const float* beta  = (const float*)d_in[25];
    float* out = (float*)d_out;

    float *h0, *h1, *n0b, *n1b, *E11, *E01, *E10, *E00, *a11, *cat0, *cat1, *stats;
    cudaGetSymbolAddress((void**)&h0,   g_h0);
    cudaGetSymbolAddress((void**)&h1,   g_h1);
    cudaGetSymbolAddress((void**)&n0b,  g_n0);
    cudaGetSymbolAddress((void**)&n1b,  g_n1);
    cudaGetSymbolAddress((void**)&E11,  g_E11);
    cudaGetSymbolAddress((void**)&E01,  g_E01);
    cudaGetSymbolAddress((void**)&E10,  g_E10);
    cudaGetSymbolAddress((void**)&E00,  g_E00);
    cudaGetSymbolAddress((void**)&a11,  g_a11);
    cudaGetSymbolAddress((void**)&cat0, g_cat0);
    cudaGetSymbolAddress((void**)&cat1, g_cat1);
    cudaGetSymbolAddress((void**)&stats, g_stats);

    const int n4 = N_NODE * EMB / 4;

    // Layer-invariant edge-embedding aggregates: E[d] = sum_{e->d} (ea[e]@We + be)
    k_zero<<<2048, 256>>>(E11, n4);
    k_zero<<<2048, 256>>>(E01, n4);
    k_zero<<<2048, 256>>>(E10, n4);
    k_zero<<<2048, 256>>>(E00, n4);
    k_edge_embed<<<2048, 256>>>(ea11, ei11 + N_EDGE, We, be, E11);
    k_edge_embed<<<2048, 256>>>(ea01, ei01 + N_EDGE, We, be, E01);
    k_edge_embed<<<2048, 256>>>(ea10, ei10 + N_EDGE, We, be, E10);
    k_edge_embed<<<2048, 256>>>(ea00, ei00 + N_EDGE, We, be, E00);

    // Input embeddings: h = x @ Wx + bx
    dim3 g1(1, (N_NODE + 127) / 128);
    dim3 g2(2, (N_NODE + 127) / 128);
    k_sgemm<<<g1, 256>>>(x0, 256, Wx, Wx, 256, 1.f, 0.f, bx, bx, h0, 128,
                         N_NODE, 256, 128, 0, nullptr);
    k_sgemm<<<g1, 256>>>(x1, 256, Wx, Wx, 256, 1.f, 0.f, bx, bx, h1, 128,
                         N_NODE, 256, 128, 0, nullptr);

    const int sgrid = (N_EDGE * 32) / 256;  // 1 warp per edge
    float* cur0 = h0;
    float* cur1 = h1;

    for (int layer = 0; layer < 2; layer++) {
        float* o0 = (layer == 0) ? n0b : h0;
        float* o1 = (layer == 0) ? n1b : h1;

        // init aggregation buffers from layer-invariant E (+ GIN self term)
        k_init_cat0<<<2048, 256>>>(cat0, E10, E00);
        k_init_cat1<<<2048, 256>>>(cat1, E01);
        k_init_a11<<<2048, 256>>>(a11, E11, cur1, n4);

        // scatter node features: agg[dst] += h[src]
        k_scatter<<<sgrid, 256>>>(cur1, ei11, ei11 + N_EDGE, a11, 128, 0);
        k_scatter<<<sgrid, 256>>>(cur0, ei01, ei01 + N_EDGE, cat1, 384, 256);
        k_scatter<<<sgrid, 256>>>(cur1, ei10, ei10 + N_EDGE, cat0, 256, 0);
        k_scatter<<<sgrid, 256>>>(cur0, ei00, ei00 + N_EDGE, cat0, 256, 128);

        // zero BN accumulators (512 floats)
        k_zero<<<1, 128>>>(stats, 128);

        // T = relu(a11 @ gW1 + gb1)  -> cat1 cols [0,256)
        k_sgemm<<<g2, 256>>>(a11, 128, gW1, gW1, 128, 1.f, 0.f, gb1, gb1,
                             cat1, 384, N_NODE, 128, 256, 1, nullptr);
        // new1 = [T | a01] @ [0.5*gW2 ; 0.05*W01] + 0.5*gb2 + 0.05*b01   (+BN stats)
        k_sgemm<<<g1, 256>>>(cat1, 384, gW2, W01, 256, 0.5f, 0.05f, gb2, b01,
                             o1, 128, N_NODE, 384, 128, 0, stats + 256);
        // new0 = [a10 | a00] @ [0.05*W10 ; 0.05*W00] + 0.05*(b10+b00)    (+BN stats)
        k_sgemm<<<g1, 256>>>(cat0, 256, W10, W00, 128, 0.05f, 0.05f, b10, b00,
                             o0, 128, N_NODE, 256, 128, 0, stats);

        k_bn_finalize<<<1, 256>>>(stats, gamma, beta, layer, 1.f / N_NODE);
        int relu = (layer == 0) ? 1 : 0;
        float* dst0 = (layer == 0) ? o0 : out;
        float* dst1 = (layer == 0) ? o1 : out + (size_t)N_NODE * EMB;
        k_bn_apply<<<2048, 256>>>(o0, dst0, N_NODE, stats + 512, relu);
        k_bn_apply<<<2048, 256>>>(o1, dst1, N_NODE, stats + 768, relu);

        cur0 = o0;
        cur1 = o1;
    }
}

// round 6
// speedup vs baseline: 1.4614x; 1.2928x over previous
#include <cuda_runtime.h>
#include <cstdint>

#define N_NODE 100000
#define N_EDGE 800000
#define EMB 128

typedef unsigned long long ull;

// ---------------- static device scratch (allocation-free) ----------------
__device__ float g_h0[N_NODE * EMB];
__device__ float g_h1[N_NODE * EMB];
__device__ float g_n0[N_NODE * EMB];
__device__ float g_n1[N_NODE * EMB];
__device__ float g_E11[N_NODE * EMB];
__device__ float g_E01[N_NODE * EMB];
__device__ float g_E10[N_NODE * EMB];
__device__ float g_E00[N_NODE * EMB];
__device__ float g_a11[N_NODE * EMB];
__device__ float g_cat0[N_NODE * 256];   // [agg10 | agg00]
__device__ float g_cat1[N_NODE * 384];   // [T(256) | agg01(128)]
__device__ float g_esum[4 * N_NODE * 16];
__device__ float g_deg[4 * N_NODE];
__device__ float g_stats[1024];

// ---------------- tiny utility kernels ----------------
__global__ void k_zero(float* __restrict__ p, int n4) {
    float4 z = make_float4(0.f, 0.f, 0.f, 0.f);
    for (int i = blockIdx.x * blockDim.x + threadIdx.x; i < n4;
         i += gridDim.x * blockDim.x)
        reinterpret_cast<float4*>(p)[i] = z;
}

__device__ __forceinline__ void red_add_v4(float* p, float4 v) {
    asm volatile("red.global.add.v4.f32 [%0], {%1,%2,%3,%4};"
                 :: "l"(p), "f"(v.x), "f"(v.y), "f"(v.z), "f"(v.w)
                 : "memory");
}
__device__ __forceinline__ void red_add_f32(float* p, float v) {
    asm volatile("red.global.add.f32 [%0], %1;" :: "l"(p), "f"(v) : "memory");
}

// ---------------- edge phase: scatter 16-wide ea sums + degree ----------------
__global__ void k_edge_sum(const float* __restrict__ ea, const int* __restrict__ dst,
                           float* __restrict__ Esum, float* __restrict__ deg) {
    const int n = N_EDGE * 4;
    for (int i = blockIdx.x * blockDim.x + threadIdx.x; i < n;
         i += gridDim.x * blockDim.x) {
        int e = i >> 2, q = i & 3;
        int d = __ldg(&dst[e]);
        float4 v = *reinterpret_cast<const float4*>(ea + (size_t)e * 16 + q * 4);
        red_add_v4(Esum + (size_t)d * 16 + q * 4, v);
        if (q == 0) red_add_f32(deg + d, 1.0f);
    }
}

// E[r] = Esum[r] @ We + deg[r]*be   (one warp per node row)
__global__ void k_edge_gemm(const float* __restrict__ Esum, const float* __restrict__ deg,
                            const float* __restrict__ We, const float* __restrict__ be,
                            float* __restrict__ Eout) {
    __shared__ float sW[16 * EMB];
    for (int i = threadIdx.x; i < 16 * EMB; i += blockDim.x) sW[i] = We[i];
    __syncthreads();
    const int lane = threadIdx.x & 31;
    const int warp = (blockIdx.x * blockDim.x + threadIdx.x) >> 5;
    const int nwarp = (gridDim.x * blockDim.x) >> 5;
    const int c0 = lane * 4;
    const float4 bev = *reinterpret_cast<const float4*>(be + c0);
    for (int r = warp; r < N_NODE; r += nwarp) {
        float av = (lane < 16) ? Esum[(size_t)r * 16 + lane] : 0.f;
        float dg = __ldg(&deg[r]);
        float4 acc = make_float4(dg * bev.x, dg * bev.y, dg * bev.z, dg * bev.w);
#pragma unroll
        for (int k = 0; k < 16; k++) {
            float a = __shfl_sync(0xffffffffu, av, k);
            float4 w = *reinterpret_cast<const float4*>(sW + k * EMB + c0);
            acc.x += a * w.x; acc.y += a * w.y; acc.z += a * w.z; acc.w += a * w.w;
        }
        *reinterpret_cast<float4*>(Eout + (size_t)r * EMB + c0) = acc;
    }
}

// ---------------- per-layer node gather/scatter: agg[dst*ldc+off] += h[src] ----------------
__global__ void k_scatter(const float* __restrict__ h, const int* __restrict__ src,
                          const int* __restrict__ dst, float* __restrict__ agg,
                          int ldc, int coloff) {
    const int lane = threadIdx.x & 31;
    const int warp = (blockIdx.x * blockDim.x + threadIdx.x) >> 5;
    if (warp >= N_EDGE) return;
    int s = __ldg(&src[warp]);
    int d = __ldg(&dst[warp]);
    float4 v = *reinterpret_cast<const float4*>(h + (size_t)s * EMB + lane * 4);
    red_add_v4(agg + (size_t)d * ldc + coloff + lane * 4, v);
}

// ---------------- fused per-layer init: cat0 <- [E10|E00], cat1[256:] <- E01,
//                  a11 <- E11 + 1.1*h1 ----------------
__global__ void k_init_layer(float* __restrict__ cat0, float* __restrict__ cat1,
                             float* __restrict__ a11,
                             const float* __restrict__ E10, const float* __restrict__ E00,
                             const float* __restrict__ E01, const float* __restrict__ E11,
                             const float* __restrict__ h1) {
    const int n = N_NODE * 32;
    for (int i = blockIdx.x * blockDim.x + threadIdx.x; i < n;
         i += gridDim.x * blockDim.x) {
        int r = i >> 5, c = i & 31;
        reinterpret_cast<float4*>(cat0)[r * 64 + c] =
            reinterpret_cast<const float4*>(E10)[i];
        reinterpret_cast<float4*>(cat0)[r * 64 + 32 + c] =
            reinterpret_cast<const float4*>(E00)[i];
        reinterpret_cast<float4*>(cat1)[r * 96 + 64 + c] =
            reinterpret_cast<const float4*>(E01)[i];
        float4 ev = reinterpret_cast<const float4*>(E11)[i];
        float4 hv = reinterpret_cast<const float4*>(h1)[i];
        ev.x += 1.1f * hv.x; ev.y += 1.1f * hv.y;
        ev.z += 1.1f * hv.z; ev.w += 1.1f * hv.w;
        reinterpret_cast<float4*>(a11)[i] = ev;
    }
}

// ---------------- f32x2 packed-FMA pipelined SGEMM ----------------
// C[M,N](ldc) = maybe_relu( A[M,K](lda) @ Bcat + s1*bias1 + s2*bias2 )
// Bcat rows [0,Kb) = s1*B1, rows [Kb,K) = s2*B2 (scaling applied pre-STS)
// If statp != null (requires N==128 grid.x==1): accumulate output col sums into
// statp[col], sumsq into statp[128+col].
__device__ __forceinline__ void ffma2(ull& d, ull a, ull b) {
    asm("fma.rn.f32x2 %0, %1, %2, %0;" : "+l"(d) : "l"(a), "l"(b));
}
__device__ __forceinline__ ull dup2(float x) {
    ull r; asm("mov.b64 %0, {%1, %1};" : "=l"(r) : "f"(x)); return r;
}

__global__ __launch_bounds__(256, 2) void k_sgemm(
    const float* __restrict__ A, int lda,
    const float* __restrict__ B1, const float* __restrict__ B2, int Kb,
    float s1, float s2,
    const float* __restrict__ bias1, const float* __restrict__ bias2,
    float* __restrict__ C, int ldc,
    int M, int K, int N, int relu, float* __restrict__ statp) {
    __shared__ float As[2][16][128];   // As[s][k][m]
    __shared__ float Bs[2][16][128];
    __shared__ float sred[256];
    const int t = threadIdx.x;
    const int rowBase = blockIdx.y * 128;
    const int colBase = blockIdx.x * 128;
    const int lrow = t >> 1, lkc = (t & 1) * 8;      // A-load mapping
    const int bkk = t >> 4, bnc = (t & 15) * 8;      // B-load mapping
    const int ty = t >> 4, tx = t & 15;

    ull acc2[4][8];
#pragma unroll
    for (int i = 0; i < 4; i++)
#pragma unroll
        for (int j = 0; j < 8; j++) acc2[i][j] = 0ull;

    float4 pa0, pa1, pb0, pb1;

#define LDG_TILE(k0)                                                          \
    do {                                                                      \
        pa0 = make_float4(0.f, 0.f, 0.f, 0.f); pa1 = pa0;                     \
        int gr = rowBase + lrow;                                              \
        if (gr < M) {                                                         \
            const float* ap = A + (size_t)gr * lda + (k0) + lkc;              \
            pa0 = *reinterpret_cast<const float4*>(ap);                       \
            pa1 = *reinterpret_cast<const float4*>(ap + 4);                   \
        }                                                                     \
        int brg = (k0) + bkk;                                                 \
        const float* Bsrc; float sc;                                          \
        if (brg < Kb) { Bsrc = B1 + (size_t)brg * N; sc = s1; }               \
        else          { Bsrc = B2 + (size_t)(brg - Kb) * N; sc = s2; }        \
        pb0 = *reinterpret_cast<const float4*>(Bsrc + colBase + bnc);         \
        pb1 = *reinterpret_cast<const float4*>(Bsrc + colBase + bnc + 4);     \
        pb0.x *= sc; pb0.y *= sc; pb0.z *= sc; pb0.w *= sc;                   \
        pb1.x *= sc; pb1.y *= sc; pb1.z *= sc; pb1.w *= sc;                   \
    } while (0)

#define STS_TILE(s)                                                           \
    do {                                                                      \
        As[s][lkc + 0][lrow] = pa0.x; As[s][lkc + 1][lrow] = pa0.y;           \
        As[s][lkc + 2][lrow] = pa0.z; As[s][lkc + 3][lrow] = pa0.w;           \
        As[s][lkc + 4][lrow] = pa1.x; As[s][lkc + 5][lrow] = pa1.y;           \
        As[s][lkc + 6][lrow] = pa1.z; As[s][lkc + 7][lrow] = pa1.w;           \
        *reinterpret_cast<float4*>(&Bs[s][bkk][bnc])     = pb0;               \
        *reinterpret_cast<float4*>(&Bs[s][bkk][bnc + 4]) = pb1;               \
    } while (0)

    LDG_TILE(0);
    STS_TILE(0);
    __syncthreads();

    const int nt = K >> 4;
    for (int kt = 0; kt < nt; kt++) {
        const int cur = kt & 1;
        if (kt + 1 < nt) LDG_TILE((kt + 1) << 4);
#pragma unroll
        for (int kk = 0; kk < 16; kk++) {
            ull a2[4];
            const ull* ap = reinterpret_cast<const ull*>(&As[cur][kk][ty * 8]);
#pragma unroll
            for (int i = 0; i < 4; i++) a2[i] = ap[i];
            float4 r0 = *reinterpret_cast<const float4*>(&Bs[cur][kk][tx * 8]);
            float4 r1 = *reinterpret_cast<const float4*>(&Bs[cur][kk][tx * 8 + 4]);
            ull b2[8];
            b2[0] = dup2(r0.x); b2[1] = dup2(r0.y);
            b2[2] = dup2(r0.z); b2[3] = dup2(r0.w);
            b2[4] = dup2(r1.x); b2[5] = dup2(r1.y);
            b2[6] = dup2(r1.z); b2[7] = dup2(r1.w);
#pragma unroll
            for (int i = 0; i < 4; i++)
#pragma unroll
                for (int j = 0; j < 8; j++) ffma2(acc2[i][j], a2[i], b2[j]);
        }
        if (kt + 1 < nt) {
            STS_TILE(cur ^ 1);
            __syncthreads();
        }
    }

    // combined bias
    float bb[8];
#pragma unroll
    for (int j = 0; j < 8; j++) {
        int gc = colBase + tx * 8 + j;
        bb[j] = s1 * bias1[gc] + s2 * bias2[gc];
    }

    float csum[8], csq[8];
#pragma unroll
    for (int j = 0; j < 8; j++) { csum[j] = 0.f; csq[j] = 0.f; }

#pragma unroll
    for (int ip = 0; ip < 4; ip++) {
        float lo[8], hi[8];
#pragma unroll
        for (int j = 0; j < 8; j++)
            asm("mov.b64 {%0,%1}, %2;" : "=f"(lo[j]), "=f"(hi[j]) : "l"(acc2[ip][j]));
#pragma unroll
        for (int half = 0; half < 2; half++) {
            float* vv = half ? hi : lo;
            int gr = rowBase + ty * 8 + 2 * ip + half;
            if (gr < M) {
                float v[8];
#pragma unroll
                for (int j = 0; j < 8; j++) {
                    v[j] = vv[j] + bb[j];
                    if (relu) v[j] = fmaxf(v[j], 0.f);
                    csum[j] += v[j];
                    csq[j] += v[j] * v[j];
                }
                float* cp = C + (size_t)gr * ldc + colBase + tx * 8;
                *reinterpret_cast<float4*>(cp)     = make_float4(v[0], v[1], v[2], v[3]);
                *reinterpret_cast<float4*>(cp + 4) = make_float4(v[4], v[5], v[6], v[7]);
            }
        }
    }

    if (statp) {
        sred[t] = 0.f;
        __syncthreads();
        int colb = tx * 8;
#pragma unroll
        for (int j = 0; j < 8; j++) {
            atomicAdd(&sred[colb + j], csum[j]);
            atomicAdd(&sred[128 + colb + j], csq[j]);
        }
        __syncthreads();
        if (t < 128) {
            atomicAdd(&statp[t], sred[t]);
            atomicAdd(&statp[128 + t], sred[128 + t]);
        }
    }
#undef LDG_TILE
#undef STS_TILE
}

// ---------------- BatchNorm finalize / apply ----------------
__global__ void k_bn_finalize(float* __restrict__ stats, const float* __restrict__ gamma,
                              const float* __restrict__ beta, int layer, float invM) {
    int c = threadIdx.x;
    int type = c >> 7, col = c & 127;
    float mu = stats[type * 256 + col] * invM;
    float var = stats[type * 256 + 128 + col] * invM - mu * mu;
    float a = gamma[layer * EMB + col] * rsqrtf(var + 1e-5f);
    float b = beta[layer * EMB + col] - a * mu;
    stats[512 + type * 256 + col] = a;
    stats[512 + type * 256 + 128 + col] = b;
}

// both node types in one pass; coef0 = stats+512, coef1 = stats+768
__global__ void k_bn_apply2(const float* __restrict__ X0, float* __restrict__ Y0,
                            const float* __restrict__ X1, float* __restrict__ Y1,
                            const float* __restrict__ stats, int relu) {
    const int n = N_NODE * EMB;
    for (int i = blockIdx.x * blockDim.x + threadIdx.x; i < 2 * n;
         i += gridDim.x * blockDim.x) {
        int col = i & 127;
        if (i < n) {
            float v = stats[512 + col] * X0[i] + stats[512 + 128 + col];
            if (relu) v = fmaxf(v, 0.f);
            Y0[i] = v;
        } else {
            int j = i - n;
            float v = stats[768 + col] * X1[j] + stats[768 + 128 + col];
            if (relu) v = fmaxf(v, 0.f);
            Y1[j] = v;
        }
    }
}

// ---------------- host orchestration ----------------
extern "C" void kernel_launch(void* const* d_in, const int* in_sizes, int n_in,
                              void* d_out, int out_size) {
    (void)in_sizes; (void)n_in; (void)out_size;
    const float* x0   = (const float*)d_in[0];
    const float* x1   = (const float*)d_in[1];
    const float* ea11 = (const float*)d_in[2];
    const float* ea10 = (const float*)d_in[3];
    const float* ea01 = (const float*)d_in[4];
    const float* ea00 = (const float*)d_in[5];
    const int*   ei11 = (const int*)d_in[6];
    const int*   ei10 = (const int*)d_in[7];
    const int*   ei01 = (const int*)d_in[8];
    const int*   ei00 = (const int*)d_in[9];
    const float* Wx  = (const float*)d_in[10];
    const float* bx  = (const float*)d_in[11];
    const float* We  = (const float*)d_in[12];
    const float* be  = (const float*)d_in[13];
    const float* gW1 = (const float*)d_in[14];
    const float* gb1 = (const float*)d_in[15];
    const float* gW2 = (const float*)d_in[16];
    const float* gb2 = (const float*)d_in[17];
    const float* W10 = (const float*)d_in[18];
    const float* b10 = (const float*)d_in[19];
    const float* W01 = (const float*)d_in[20];
    const float* b01 = (const float*)d_in[21];
    const float* W00 = (const float*)d_in[22];
    const float* b00 = (const float*)d_in[23];
    const float* gamma = (const float*)d_in[24];
    const float* beta  = (const float*)d_in[25];
    float* out = (float*)d_out;

    float *h0, *h1, *n0b, *n1b, *E11, *E01, *E10, *E00, *a11, *cat0, *cat1;
    float *esum, *deg, *stats;
    cudaGetSymbolAddress((void**)&h0,   g_h0);
    cudaGetSymbolAddress((void**)&h1,   g_h1);
    cudaGetSymbolAddress((void**)&n0b,  g_n0);
    cudaGetSymbolAddress((void**)&n1b,  g_n1);
    cudaGetSymbolAddress((void**)&E11,  g_E11);
    cudaGetSymbolAddress((void**)&E01,  g_E01);
    cudaGetSymbolAddress((void**)&E10,  g_E10);
    cudaGetSymbolAddress((void**)&E00,  g_E00);
    cudaGetSymbolAddress((void**)&a11,  g_a11);
    cudaGetSymbolAddress((void**)&cat0, g_cat0);
    cudaGetSymbolAddress((void**)&cat1, g_cat1);
    cudaGetSymbolAddress((void**)&esum, g_esum);
    cudaGetSymbolAddress((void**)&deg,  g_deg);
    cudaGetSymbolAddress((void**)&stats, g_stats);

    // ---- edge phase: 16-wide sums + degree, then tiny GEMV per node ----
    k_zero<<<2048, 256>>>(esum, 4 * N_NODE * 4);           // 4*N*16 floats
    k_zero<<<512, 256>>>(deg, N_NODE);                     // 4*N floats
    k_edge_sum<<<1600, 256>>>(ea11, ei11 + N_EDGE, esum + 0 * N_NODE * 16, deg + 0 * N_NODE);
    k_edge_sum<<<1600, 256>>>(ea01, ei01 + N_EDGE, esum + 1 * N_NODE * 16, deg + 1 * N_NODE);
    k_edge_sum<<<1600, 256>>>(ea10, ei10 + N_EDGE, esum + 2 * N_NODE * 16, deg + 2 * N_NODE);
    k_edge_sum<<<1600, 256>>>(ea00, ei00 + N_EDGE, esum + 3 * N_NODE * 16, deg + 3 * N_NODE);
    k_edge_gemm<<<1024, 256>>>(esum + 0 * N_NODE * 16, deg + 0 * N_NODE, We, be, E11);
    k_edge_gemm<<<1024, 256>>>(esum + 1 * N_NODE * 16, deg + 1 * N_NODE, We, be, E01);
    k_edge_gemm<<<1024, 256>>>(esum + 2 * N_NODE * 16, deg + 2 * N_NODE, We, be, E10);
    k_edge_gemm<<<1024, 256>>>(esum + 3 * N_NODE * 16, deg + 3 * N_NODE, We, be, E00);

    // Input embeddings: h = x @ Wx + bx
    dim3 g1(1, (N_NODE + 127) / 128);
    dim3 g2(2, (N_NODE + 127) / 128);
    k_sgemm<<<g1, 256>>>(x0, 256, Wx, Wx, 256, 1.f, 0.f, bx, bx, h0, 128,
                         N_NODE, 256, 128, 0, nullptr);
    k_sgemm<<<g1, 256>>>(x1, 256, Wx, Wx, 256, 1.f, 0.f, bx, bx, h1, 128,
                         N_NODE, 256, 128, 0, nullptr);

    const int sgrid = (N_EDGE * 32) / 256;  // 1 warp per edge
    float* cur0 = h0;
    float* cur1 = h1;

    for (int layer = 0; layer < 2; layer++) {
        float* o0 = (layer == 0) ? n0b : h0;
        float* o1 = (layer == 0) ? n1b : h1;

        // init aggregation buffers from layer-invariant E (+ GIN self term)
        k_init_layer<<<2048, 256>>>(cat0, cat1, a11, E10, E00, E01, E11, cur1);

        // scatter node features: agg[dst] += h[src]
        k_scatter<<<sgrid, 256>>>(cur1, ei11, ei11 + N_EDGE, a11, 128, 0);
        k_scatter<<<sgrid, 256>>>(cur0, ei01, ei01 + N_EDGE, cat1, 384, 256);
        k_scatter<<<sgrid, 256>>>(cur1, ei10, ei10 + N_EDGE, cat0, 256, 0);
        k_scatter<<<sgrid, 256>>>(cur0, ei00, ei00 + N_EDGE, cat0, 256, 128);

        // zero BN accumulators (512 floats)
        k_zero<<<1, 128>>>(stats, 128);

        // T = relu(a11 @ gW1 + gb1)  -> cat1 cols [0,256)
        k_sgemm<<<g2, 256>>>(a11, 128, gW1, gW1, 128, 1.f, 0.f, gb1, gb1,
                             cat1, 384, N_NODE, 128, 256, 1, nullptr);
        // new1 = [T | a01] @ [0.5*gW2 ; 0.05*W01] + 0.5*gb2 + 0.05*b01   (+BN stats)
        k_sgemm<<<g1, 256>>>(cat1, 384, gW2, W01, 256, 0.5f, 0.05f, gb2, b01,
                             o1, 128, N_NODE, 384, 128, 0, stats + 256);
        // new0 = [a10 | a00] @ [0.05*W10 ; 0.05*W00] + 0.05*(b10+b00)    (+BN stats)
        k_sgemm<<<g1, 256>>>(cat0, 256, W10, W00, 128, 0.05f, 0.05f, b10, b00,
                             o0, 128, N_NODE, 256, 128, 0, stats);

        k_bn_finalize<<<1, 256>>>(stats, gamma, beta, layer, 1.f / N_NODE);
        int relu = (layer == 0) ? 1 : 0;
        float* dst0 = (layer == 0) ? o0 : out;
        float* dst1 = (layer == 0) ? o1 : out + (size_t)N_NODE * EMB;
        k_bn_apply2<<<2048, 256>>>(o0, dst0, o1, dst1, stats, relu);

        cur0 = o0;
        cur1 = o1;
    }
}

// round 9
// speedup vs baseline: 1.8672x; 1.2777x over previous
#include <cuda_runtime.h>
#include <cuda_bf16.h>
#include <cstdint>

#define N_NODE 100000
#define N_EDGE 800000
#define EMB 128
#define PITCH 40   // bf16 elems per smem row: 32 data + 8 pad = 80 bytes

// ---------------- static device scratch (allocation-free) ----------------
__device__ float g_h0[N_NODE * EMB];
__device__ float g_h1[N_NODE * EMB];
__device__ float g_n0[N_NODE * EMB];
__device__ float g_n1[N_NODE * EMB];
__device__ float g_E11[N_NODE * EMB];
__device__ float g_E01[N_NODE * EMB];
__device__ float g_E10[N_NODE * EMB];
__device__ float g_E00[N_NODE * EMB];
__device__ float g_a11[N_NODE * EMB];
__device__ float g_cat0[N_NODE * 256];   // [agg10 | agg00]
__device__ float g_cat1[N_NODE * 384];   // [T(256) | agg01(128)]
__device__ float g_esum[4 * N_NODE * 16];
__device__ float g_deg[4 * N_NODE];
__device__ float g_stats[1024];
// pre-transposed / pre-split / pre-scaled weights: [N][K] bf16 hi/lo
__device__ __align__(16) __nv_bfloat16 g_bth[147456];
__device__ __align__(16) __nv_bfloat16 g_btl[147456];
__device__ float g_biasc[1024];

// ---------------- tiny utility kernels ----------------
__global__ void k_zero(float* __restrict__ p, int n4) {
    float4 z = make_float4(0.f, 0.f, 0.f, 0.f);
    for (int i = blockIdx.x * blockDim.x + threadIdx.x; i < n4;
         i += gridDim.x * blockDim.x)
        reinterpret_cast<float4*>(p)[i] = z;
}

__device__ __forceinline__ void red_add_v4(float* p, float4 v) {
    asm volatile("red.global.add.v4.f32 [%0], {%1,%2,%3,%4};"
                 :: "l"(p), "f"(v.x), "f"(v.y), "f"(v.z), "f"(v.w)
                 : "memory");
}
__device__ __forceinline__ void red_add_f32(float* p, float v) {
    asm volatile("red.global.add.f32 [%0], %1;" :: "l"(p), "f"(v) : "memory");
}

// ---------------- edge phase: scatter 16-wide ea sums + degree ----------------
__global__ void k_edge_sum(const float* __restrict__ ea, const int* __restrict__ dst,
                           float* __restrict__ Esum, float* __restrict__ deg) {
    const int n = N_EDGE * 4;
    for (int i = blockIdx.x * blockDim.x + threadIdx.x; i < n;
         i += gridDim.x * blockDim.x) {
        int e = i >> 2, q = i & 3;
        int d = __ldg(&dst[e]);
        float4 v = *reinterpret_cast<const float4*>(ea + (size_t)e * 16 + q * 4);
        red_add_v4(Esum + (size_t)d * 16 + q * 4, v);
        if (q == 0) red_add_f32(deg + d, 1.0f);
    }
}

// E[r] = Esum[r] @ We + deg[r]*be   (one warp per node row)
__global__ void k_edge_gemm(const float* __restrict__ Esum, const float* __restrict__ deg,
                            const float* __restrict__ We, const float* __restrict__ be,
                            float* __restrict__ Eout) {
    __shared__ float sW[16 * EMB];
    for (int i = threadIdx.x; i < 16 * EMB; i += blockDim.x) sW[i] = We[i];
    __syncthreads();
    const int lane = threadIdx.x & 31;
    const int warp = (blockIdx.x * blockDim.x + threadIdx.x) >> 5;
    const int nwarp = (gridDim.x * blockDim.x) >> 5;
    const int c0 = lane * 4;
    const float4 bev = *reinterpret_cast<const float4*>(be + c0);
    for (int r = warp; r < N_NODE; r += nwarp) {
        float av = (lane < 16) ? Esum[(size_t)r * 16 + lane] : 0.f;
        float dg = __ldg(&deg[r]);
        float4 acc = make_float4(dg * bev.x, dg * bev.y, dg * bev.z, dg * bev.w);
#pragma unroll
        for (int k = 0; k < 16; k++) {
            float a = __shfl_sync(0xffffffffu, av, k);
            float4 w = *reinterpret_cast<const float4*>(sW + k * EMB + c0);
            acc.x += a * w.x; acc.y += a * w.y; acc.z += a * w.z; acc.w += a * w.w;
        }
        *reinterpret_cast<float4*>(Eout + (size_t)r * EMB + c0) = acc;
    }
}

// ---------------- per-layer node gather/scatter ----------------
__global__ void k_scatter(const float* __restrict__ h, const int* __restrict__ src,
                          const int* __restrict__ dst, float* __restrict__ agg,
                          int ldc, int coloff) {
    const int lane = threadIdx.x & 31;
    const int warp = (blockIdx.x * blockDim.x + threadIdx.x) >> 5;
    if (warp >= N_EDGE) return;
    int s = __ldg(&src[warp]);
    int d = __ldg(&dst[warp]);
    float4 v = *reinterpret_cast<const float4*>(h + (size_t)s * EMB + lane * 4);
    red_add_v4(agg + (size_t)d * ldc + coloff + lane * 4, v);
}

// ---------------- fused per-layer init ----------------
__global__ void k_init_layer(float* __restrict__ cat0, float* __restrict__ cat1,
                             float* __restrict__ a11,
                             const float* __restrict__ E10, const float* __restrict__ E00,
                             const float* __restrict__ E01, const float* __restrict__ E11,
                             const float* __restrict__ h1) {
    const int n = N_NODE * 32;
    for (int i = blockIdx.x * blockDim.x + threadIdx.x; i < n;
         i += gridDim.x * blockDim.x) {
        int r = i >> 5, c = i & 31;
        reinterpret_cast<float4*>(cat0)[r * 64 + c] =
            reinterpret_cast<const float4*>(E10)[i];
        reinterpret_cast<float4*>(cat0)[r * 64 + 32 + c] =
            reinterpret_cast<const float4*>(E00)[i];
        reinterpret_cast<float4*>(cat1)[r * 96 + 64 + c] =
            reinterpret_cast<const float4*>(E01)[i];
        float4 ev = reinterpret_cast<const float4*>(E11)[i];
        float4 hv = reinterpret_cast<const float4*>(h1)[i];
        ev.x += 1.1f * hv.x; ev.y += 1.1f * hv.y;
        ev.z += 1.1f * hv.z; ev.w += 1.1f * hv.w;
        reinterpret_cast<float4*>(a11)[i] = ev;
    }
}

// ---------------- weight prep: Bcat -> [N][K] bf16 hi/lo, scaled; combined bias ----------------
__global__ void k_prep(const float* __restrict__ B1, const float* __restrict__ B2,
                       int Kb, int K, int Ngm, int Nout, float s1, float s2,
                       const float* __restrict__ b1, const float* __restrict__ b2,
                       __nv_bfloat16* __restrict__ oh, __nv_bfloat16* __restrict__ ol,
                       float* __restrict__ ob) {
    const int tot = Nout * K;
    for (int i = blockIdx.x * blockDim.x + threadIdx.x; i < tot;
         i += gridDim.x * blockDim.x) {
        int n = i / K, k = i - n * K;
        float v = (k < Kb) ? s1 * B1[(size_t)k * Ngm + n]
                           : s2 * B2[(size_t)(k - Kb) * Ngm + n];
        __nv_bfloat16 h = __float2bfloat16(v);
        oh[i] = h;
        ol[i] = __float2bfloat16(v - __bfloat162float(h));
        if (k == 0) ob[n] = s1 * b1[n] + s2 * b2[n];
    }
}

// ---------------- warp-MMA split-bf16 GEMM (legacy HMMA path, sm_80+) ----------------
__device__ __forceinline__ uint32_t s2u(const void* p) {
    uint32_t a;
    asm("{ .reg .u64 t; cvta.to.shared.u64 t, %1; cvt.u32.u64 %0, t; }"
        : "=r"(a) : "l"(p));
    return a;
}
__device__ __forceinline__ void ldsm4(uint32_t* r, uint32_t addr) {
    asm volatile("ldmatrix.sync.aligned.m8n8.x4.shared.b16 {%0,%1,%2,%3}, [%4];"
                 : "=r"(r[0]), "=r"(r[1]), "=r"(r[2]), "=r"(r[3]) : "r"(addr));
}
__device__ __forceinline__ void ldsm2(uint32_t* r, uint32_t addr) {
    asm volatile("ldmatrix.sync.aligned.m8n8.x2.shared.b16 {%0,%1}, [%2];"
                 : "=r"(r[0]), "=r"(r[1]) : "r"(addr));
}
__device__ __forceinline__ void mma16816(float* c, const uint32_t* a, const uint32_t* b) {
    asm volatile(
        "mma.sync.aligned.m16n8k16.row.col.f32.bf16.bf16.f32 "
        "{%0,%1,%2,%3}, {%4,%5,%6,%7}, {%8,%9}, {%0,%1,%2,%3};"
        : "+f"(c[0]), "+f"(c[1]), "+f"(c[2]), "+f"(c[3])
        : "r"(a[0]), "r"(a[1]), "r"(a[2]), "r"(a[3]), "r"(b[0]), "r"(b[1]));
}
__device__ __forceinline__ uint32_t pk2(float a, float b) {
    __nv_bfloat162 h = __floats2bfloat162_rn(a, b);
    return *reinterpret_cast<uint32_t*>(&h);
}

// C[M, 128*gridx](ldc) = maybe_relu(A[M,K](lda) @ W + biasc); W pre-split [N][K]
__global__ __launch_bounds__(256, 2) void k_mma_gemm(
    const float* __restrict__ A, int lda, int M, int K,
    const __nv_bfloat16* __restrict__ Bh, const __nv_bfloat16* __restrict__ Bl,
    const float* __restrict__ biasc,
    float* __restrict__ C, int ldc, int relu) {
    __shared__ __nv_bfloat16 sAh[128 * PITCH], sAl[128 * PITCH];
    __shared__ __nv_bfloat16 sBh[128 * PITCH], sBl[128 * PITCH];
    const int t = threadIdx.x, lane = t & 31, wid = t >> 5;
    const int rowBase = blockIdx.y * 128;
    const int n0g = blockIdx.x * 128;
    const int wm = (wid >> 1) * 32, wn = (wid & 1) * 64;
    const uint32_t uAh = s2u(sAh), uAl = s2u(sAl);
    const uint32_t uBh = s2u(sBh), uBl = s2u(sBl);

    float acc[2][8][4];
#pragma unroll
    for (int i = 0; i < 2; i++)
#pragma unroll
        for (int j = 0; j < 8; j++)
#pragma unroll
            for (int q = 0; q < 4; q++) acc[i][j][q] = 0.f;

    // lane roles for ldmatrix address generation
    const int li = lane & 7;
    const int a_row = (lane >> 3 & 1) * 8 + li;       // x4: row offset within 16
    const int a_kof = (lane >> 4) * 8;                // x4: k offset (0/8)
    const int b_row = li;                             // x2: row within 8
    const int b_kof = ((lane >> 3) & 1) * 8;          // x2: k offset (0/8)

    const int arow = t >> 1, acol = (t & 1) * 16;     // A loader mapping

    for (int k0 = 0; k0 < K; k0 += 32) {
        // ---- A: 128x32 f32 -> split bf16 hi/lo ----
        {
            const int gr = rowBase + arow;
            float f[16];
            if (gr < M) {
                const float* ap = A + (size_t)gr * lda + k0 + acol;
#pragma unroll
                for (int q = 0; q < 4; q++) {
                    float4 v = __ldg(reinterpret_cast<const float4*>(ap + q * 4));
                    f[4 * q] = v.x; f[4 * q + 1] = v.y;
                    f[4 * q + 2] = v.z; f[4 * q + 3] = v.w;
                }
            } else {
#pragma unroll
                for (int q = 0; q < 16; q++) f[q] = 0.f;
            }
            uint32_t h[8], l[8];
#pragma unroll
            for (int q = 0; q < 8; q++) {
                float x0 = f[2 * q], x1 = f[2 * q + 1];
                float r0 = x0 - __bfloat162float(__float2bfloat16(x0));
                float r1 = x1 - __bfloat162float(__float2bfloat16(x1));
                h[q] = pk2(x0, x1);
                l[q] = pk2(r0, r1);
            }
            __nv_bfloat16* dh = sAh + arow * PITCH + acol;
            __nv_bfloat16* dl = sAl + arow * PITCH + acol;
            reinterpret_cast<uint4*>(dh)[0] = make_uint4(h[0], h[1], h[2], h[3]);
            reinterpret_cast<uint4*>(dh)[1] = make_uint4(h[4], h[5], h[6], h[7]);
            reinterpret_cast<uint4*>(dl)[0] = make_uint4(l[0], l[1], l[2], l[3]);
            reinterpret_cast<uint4*>(dl)[1] = make_uint4(l[4], l[5], l[6], l[7]);
        }
        // ---- B: 128x32 bf16 hi/lo (pre-split, [N][K]) ----
        {
            const int brow = t >> 1, bcol = (t & 1) * 16;
            const size_t go = (size_t)(n0g + brow) * K + k0 + bcol;
            const uint4* bhp = reinterpret_cast<const uint4*>(Bh + go);
            const uint4* blp = reinterpret_cast<const uint4*>(Bl + go);
            __nv_bfloat16* dh = sBh + brow * PITCH + bcol;
            __nv_bfloat16* dl = sBl + brow * PITCH + bcol;
            reinterpret_cast<uint4*>(dh)[0] = __ldg(bhp);
            reinterpret_cast<uint4*>(dh)[1] = __ldg(bhp + 1);
            reinterpret_cast<uint4*>(dl)[0] = __ldg(blp);
            reinterpret_cast<uint4*>(dl)[1] = __ldg(blp + 1);
        }
        __syncthreads();

#pragma unroll
        for (int ks = 0; ks < 32; ks += 16) {
            uint32_t ah[2][4], al[2][4];
#pragma unroll
            for (int mt = 0; mt < 2; mt++) {
                uint32_t off = ((wm + mt * 16 + a_row) * PITCH + ks + a_kof) * 2;
                ldsm4(ah[mt], uAh + off);
                ldsm4(al[mt], uAl + off);
            }
#pragma unroll
            for (int nt = 0; nt < 8; nt++) {
                uint32_t bh[2], bl[2];
                uint32_t off = ((wn + nt * 8 + b_row) * PITCH + ks + b_kof) * 2;
                ldsm2(bh, uBh + off);
                ldsm2(bl, uBl + off);
#pragma unroll
                for (int mt = 0; mt < 2; mt++) {
                    mma16816(acc[mt][nt], ah[mt], bh);
                    mma16816(acc[mt][nt], ah[mt], bl);
                    mma16816(acc[mt][nt], al[mt], bh);
                }
            }
        }
        __syncthreads();
    }

    // ---- epilogue: bias + relu, write f32 ----
    const int r4 = lane >> 2, c2 = (lane & 3) * 2;
#pragma unroll
    for (int mt = 0; mt < 2; mt++) {
        const int row0 = rowBase + wm + mt * 16 + r4;
        const int row1 = row0 + 8;
#pragma unroll
        for (int nt = 0; nt < 8; nt++) {
            const int col = n0g + wn + nt * 8 + c2;
            float b0 = __ldg(biasc + col), b1 = __ldg(biasc + col + 1);
            float v0 = acc[mt][nt][0] + b0, v1 = acc[mt][nt][1] + b1;
            float v2 = acc[mt][nt][2] + b0, v3 = acc[mt][nt][3] + b1;
            if (relu) {
                v0 = fmaxf(v0, 0.f); v1 = fmaxf(v1, 0.f);
                v2 = fmaxf(v2, 0.f); v3 = fmaxf(v3, 0.f);
            }
            if (row0 < M)
                *reinterpret_cast<float2*>(C + (size_t)row0 * ldc + col) =
                    make_float2(v0, v1);
            if (row1 < M)
                *reinterpret_cast<float2*>(C + (size_t)row1 * ldc + col) =
                    make_float2(v2, v3);
        }
    }
}

// ---------------- BatchNorm ----------------
__global__ void k_bn_stats(const float* __restrict__ X, int M, float* __restrict__ stats) {
    const int col = threadIdx.x & 127;
    const int rp = threadIdx.x >> 7;
    float s = 0.f, q = 0.f;
    for (int r = blockIdx.x * 2 + rp; r < M; r += gridDim.x * 2) {
        float v = X[(size_t)r * EMB + col];
        s += v; q += v * v;
    }
    atomicAdd(&stats[col], s);
    atomicAdd(&stats[EMB + col], q);
}

__global__ void k_bn_finalize(float* __restrict__ stats, const float* __restrict__ gamma,
                              const float* __restrict__ beta, int layer, float invM) {
    int c = threadIdx.x;
    int type = c >> 7, col = c & 127;
    float mu = stats[type * 256 + col] * invM;
    float var = stats[type * 256 + 128 + col] * invM - mu * mu;
    float a = gamma[layer * EMB + col] * rsqrtf(var + 1e-5f);
    float b = beta[layer * EMB + col] - a * mu;
    stats[512 + type * 256 + col] = a;
    stats[512 + type * 256 + 128 + col] = b;
}

__global__ void k_bn_apply2(const float* __restrict__ X0, float* __restrict__ Y0,
                            const float* __restrict__ X1, float* __restrict__ Y1,
                            const float* __restrict__ stats, int relu) {
    const int n = N_NODE * EMB;
    for (int i = blockIdx.x * blockDim.x + threadIdx.x; i < 2 * n;
         i += gridDim.x * blockDim.x) {
        int col = i & 127;
        if (i < n) {
            float v = stats[512 + col] * X0[i] + stats[512 + 128 + col];
            if (relu) v = fmaxf(v, 0.f);
            Y0[i] = v;
        } else {
            int j = i - n;
            float v = stats[768 + col] * X1[j] + stats[768 + 128 + col];
            if (relu) v = fmaxf(v, 0.f);
            Y1[j] = v;
        }
    }
}

// ---------------- host orchestration ----------------
extern "C" void kernel_launch(void* const* d_in, const int* in_sizes, int n_in,
                              void* d_out, int out_size) {
    (void)in_sizes; (void)n_in; (void)out_size;
    const float* x0   = (const float*)d_in[0];
    const float* x1   = (const float*)d_in[1];
    const float* ea11 = (const float*)d_in[2];
    const float* ea10 = (const float*)d_in[3];
    const float* ea01 = (const float*)d_in[4];
    const float* ea00 = (const float*)d_in[5];
    const int*   ei11 = (const int*)d_in[6];
    const int*   ei10 = (const int*)d_in[7];
    const int*   ei01 = (const int*)d_in[8];
    const int*   ei00 = (const int*)d_in[9];
    const float* Wx  = (const float*)d_in[10];
    const float* bx  = (const float*)d_in[11];
    const float* We  = (const float*)d_in[12];
    const float* be  = (const float*)d_in[13];
    const float* gW1 = (const float*)d_in[14];
    const float* gb1 = (const float*)d_in[15];
    const float* gW2 = (const float*)d_in[16];
    const float* gb2 = (const float*)d_in[17];
    const float* W10 = (const float*)d_in[18];
    const float* b10 = (const float*)d_in[19];
    const float* W01 = (const float*)d_in[20];
    const float* b01 = (const float*)d_in[21];
    const float* W00 = (const float*)d_in[22];
    const float* b00 = (const float*)d_in[23];
    const float* gamma = (const float*)d_in[24];
    const float* beta  = (const float*)d_in[25];
    float* out = (float*)d_out;

    float *h0, *h1, *n0b, *n1b, *E11, *E01, *E10, *E00, *a11, *cat0, *cat1;
    float *esum, *deg, *stats, *biasc;
    __nv_bfloat16 *bth, *btl;
    cudaGetSymbolAddress((void**)&h0,   g_h0);
    cudaGetSymbolAddress((void**)&h1,   g_h1);
    cudaGetSymbolAddress((void**)&n0b,  g_n0);
    cudaGetSymbolAddress((void**)&n1b,  g_n1);
    cudaGetSymbolAddress((void**)&E11,  g_E11);
    cudaGetSymbolAddress((void**)&E01,  g_E01);
    cudaGetSymbolAddress((void**)&E10,  g_E10);
    cudaGetSymbolAddress((void**)&E00,  g_E00);
    cudaGetSymbolAddress((void**)&a11,  g_a11);
    cudaGetSymbolAddress((void**)&cat0, g_cat0);
    cudaGetSymbolAddress((void**)&cat1, g_cat1);
    cudaGetSymbolAddress((void**)&esum, g_esum);
    cudaGetSymbolAddress((void**)&deg,  g_deg);
    cudaGetSymbolAddress((void**)&stats, g_stats);
    cudaGetSymbolAddress((void**)&bth,  g_bth);
    cudaGetSymbolAddress((void**)&btl,  g_btl);
    cudaGetSymbolAddress((void**)&biasc, g_biasc);

    // ---- weight prep (tiny, once per launch) ----
    k_prep<<<128, 256>>>(Wx, Wx, 256, 256, 128, 128, 1.f, 0.f, bx, bx,
                         bth, btl, biasc);
    k_prep<<<128, 256>>>(gW1, gW1, 128, 128, 256, 256, 1.f, 0.f, gb1, gb1,
                         bth + 32768, btl + 32768, biasc + 256);
    k_prep<<<192, 256>>>(gW2, W01, 256, 384, 128, 128, 0.5f, 0.05f, gb2, b01,
                         bth + 65536, btl + 65536, biasc + 512);
    k_prep<<<128, 256>>>(W10, W00, 128, 256, 128, 128, 0.05f, 0.05f, b10, b00,
                         bth + 114688, btl + 114688, biasc + 768);

    // ---- edge phase: 16-wide sums + degree, then tiny GEMV per node ----
    k_zero<<<2048, 256>>>(esum, 4 * N_NODE * 4);
    k_zero<<<512, 256>>>(deg, N_NODE);
    k_edge_sum<<<1600, 256>>>(ea11, ei11 + N_EDGE, esum + 0 * N_NODE * 16, deg + 0 * N_NODE);
    k_edge_sum<<<1600, 256>>>(ea01, ei01 + N_EDGE, esum + 1 * N_NODE * 16, deg + 1 * N_NODE);
    k_edge_sum<<<1600, 256>>>(ea10, ei10 + N_EDGE, esum + 2 * N_NODE * 16, deg + 2 * N_NODE);
    k_edge_sum<<<1600, 256>>>(ea00, ei00 + N_EDGE, esum + 3 * N_NODE * 16, deg + 3 * N_NODE);
    k_edge_gemm<<<1024, 256>>>(esum + 0 * N_NODE * 16, deg + 0 * N_NODE, We, be, E11);
    k_edge_gemm<<<1024, 256>>>(esum + 1 * N_NODE * 16, deg + 1 * N_NODE, We, be, E01);
    k_edge_gemm<<<1024, 256>>>(esum + 2 * N_NODE * 16, deg + 2 * N_NODE, We, be, E10);
    k_edge_gemm<<<1024, 256>>>(esum + 3 * N_NODE * 16, deg + 3 * N_NODE, We, be, E00);

    const int MT = (N_NODE + 127) / 128;   // 782 row tiles
    dim3 gg1(1, MT), gg2(2, MT);

    // Input embeddings: h = x @ Wx + bx
    k_mma_gemm<<<gg1, 256>>>(x0, 256, N_NODE, 256, bth, btl, biasc, h0, 128, 0);
    k_mma_gemm<<<gg1, 256>>>(x1, 256, N_NODE, 256, bth, btl, biasc, h1, 128, 0);

    const int sgrid = (N_EDGE * 32) / 256;  // 1 warp per edge
    float* cur0 = h0;
    float* cur1 = h1;

    for (int layer = 0; layer < 2; layer++) {
        float* o0 = (layer == 0) ? n0b : h0;
        float* o1 = (layer == 0) ? n1b : h1;

        k_init_layer<<<2048, 256>>>(cat0, cat1, a11, E10, E00, E01, E11, cur1);

        k_scatter<<<sgrid, 256>>>(cur1, ei11, ei11 + N_EDGE, a11, 128, 0);
        k_scatter<<<sgrid, 256>>>(cur0, ei01, ei01 + N_EDGE, cat1, 384, 256);
        k_scatter<<<sgrid, 256>>>(cur1, ei10, ei10 + N_EDGE, cat0, 256, 0);
        k_scatter<<<sgrid, 256>>>(cur0, ei00, ei00 + N_EDGE, cat0, 256, 128);

        // T = relu(a11 @ gW1 + gb1) -> cat1 cols [0,256)
        k_mma_gemm<<<gg2, 256>>>(a11, 128, N_NODE, 128,
                                 bth + 32768, btl + 32768, biasc + 256,
                                 cat1, 384, 1);
        // new1 = [T | a01] @ [0.5*gW2 ; 0.05*W01] + combined bias
        k_mma_gemm<<<gg1, 256>>>(cat1, 384, N_NODE, 384,
                                 bth + 65536, btl + 65536, biasc + 512,
                                 o1, 128, 0);
        // new0 = [a10 | a00] @ [0.05*W10 ; 0.05*W00] + combined bias
        k_mma_gemm<<<gg1, 256>>>(cat0, 256, N_NODE, 256,
                                 bth + 114688, btl + 114688, biasc + 768,
                                 o0, 128, 0);

        // BatchNorm
        k_zero<<<1, 128>>>(stats, 128);
        k_bn_stats<<<1024, 256>>>(o0, N_NODE, stats);
        k_bn_stats<<<1024, 256>>>(o1, N_NODE, stats + 256);
        k_bn_finalize<<<1, 256>>>(stats, gamma, beta, layer, 1.f / N_NODE);
        int relu = (layer == 0) ? 1 : 0;
        float* dst0 = (layer == 0) ? o0 : out;
        float* dst1 = (layer == 0) ? o1 : out + (size_t)N_NODE * EMB;
        k_bn_apply2<<<2048, 256>>>(o0, dst0, o1, dst1, stats, relu);

        cur0 = o0;
        cur1 = o1;
    }
}